// round 4
// baseline (speedup 1.0000x reference)
#include <cuda_runtime.h>
#include <cuda_bf16.h>
#include <stdint.h>

#define FFEAT   32
#define DDIM    64
#define P_PAIRS 496
#define FD      (FFEAT * DDIM)   // 2048
#define MT      128
#define THREADS 256

#define APITCH  72                 // bf16 elems per row (144 B, conflict-free ldmatrix)
#define ROWB    (APITCH * 2)       // 144 bytes
#define SM_AH   0
#define SM_AL   (SM_AH + MT * ROWB)            // 18432
#define SM_W0   (SM_AL + MT * ROWB)            // 36864 : W buffers
#define WBUF_HI(b) (SM_W0 + (b) * 18432)
#define WBUF_LO(b) (WBUF_HI(b) + 9216)
#define SMEM_BYTES (SM_W0 + 2 * 18432)         // 73728

static __device__ __forceinline__ uint32_t smem_u32(const void* p) {
    uint32_t a;
    asm("{ .reg .u64 t; cvta.to.shared.u64 t, %1; cvt.u32.u64 %0, t; }" : "=r"(a) : "l"(p));
    return a;
}
static __device__ __forceinline__ uint32_t packbf(float lo_e, float hi_e) {
    uint32_t r;
    asm("cvt.rn.bf16x2.f32 %0, %1, %2;" : "=r"(r) : "f"(hi_e), "f"(lo_e));
    return r;
}
static __device__ __forceinline__ float bf_rt(float x) {
    return __bfloat162float(__float2bfloat16(x));
}

#define LDSM_X4(r, addr)                                                     \
    asm volatile("ldmatrix.sync.aligned.m8n8.x4.shared.b16 {%0,%1,%2,%3}, [%4];" \
        : "=r"((r)[0]), "=r"((r)[1]), "=r"((r)[2]), "=r"((r)[3]) : "r"(addr))
#define LDSM_X4_T(r, addr)                                                   \
    asm volatile("ldmatrix.sync.aligned.m8n8.x4.trans.shared.b16 {%0,%1,%2,%3}, [%4];" \
        : "=r"((r)[0]), "=r"((r)[1]), "=r"((r)[2]), "=r"((r)[3]) : "r"(addr))
#define MMA16816(d, a, b)                                                    \
    asm volatile("mma.sync.aligned.m16n8k16.row.col.f32.bf16.bf16.f32 "      \
        "{%0,%1,%2,%3},{%4,%5,%6,%7},{%8,%9},{%0,%1,%2,%3};"                 \
        : "+f"((d)[0]), "+f"((d)[1]), "+f"((d)[2]), "+f"((d)[3])             \
        : "r"((a)[0]), "r"((a)[1]), "r"((a)[2]), "r"((a)[3]),                \
          "r"((b)[0]), "r"((b)[1]))

// convert 4 prefetched float4s of W into bf16 hi/lo smem buffer
static __device__ __forceinline__ void w_convert(char* smem, int buf, int tid,
                                                 const float4 wreg[4]) {
    #pragma unroll
    for (int t = 0; t < 4; t++) {
        const int idx4 = tid + (t << 8);        // 0..1023
        const int k  = idx4 >> 4;
        const int e4 = (idx4 & 15) << 2;
        float4 v = wreg[t];
        uint2 h = make_uint2(packbf(v.x, v.y), packbf(v.z, v.w));
        uint2 l = make_uint2(packbf(v.x - bf_rt(v.x), v.y - bf_rt(v.y)),
                             packbf(v.z - bf_rt(v.z), v.w - bf_rt(v.w)));
        const uint32_t off = (uint32_t)(k * ROWB + e4 * 2);
        *(uint2*)(smem + WBUF_HI(buf) + off) = h;
        *(uint2*)(smem + WBUF_LO(buf) + off) = l;
    }
}
static __device__ __forceinline__ void w_prefetch(const float* __restrict__ W,
                                                  int p, int tid, float4 wreg[4]) {
    const float4* wg = (const float4*)(W + (size_t)p * DDIM * DDIM);
    #pragma unroll
    for (int t = 0; t < 4; t++) wreg[t] = wg[tid + (t << 8)];
}

__global__ void __launch_bounds__(THREADS, 2)
bilin_hmma2(const float* __restrict__ X,   // [B, 32, 64]
            const float* __restrict__ W,   // [496, 64, 64]
            float* __restrict__ out)       // [B, 496, 64]
{
    extern __shared__ char smem[];
    const uint32_t sb  = smem_u32(smem);
    const int tid  = threadIdx.x;
    const int wid  = tid >> 5;
    const int lane = tid & 31;
    const int y    = blockIdx.y;           // 0..15
    const int b0   = blockIdx.x * MT;

    const int nI = (y == 15) ? 1 : 2;

    for (int s = 0; s < nI; s++) {
        const int i = (s == 0) ? y : 30 - y;
        const int pbase = i * (63 - i) / 2 - i - 1;   // p = pbase + j
        const int j0 = i + 1;

        if (s > 0) __syncthreads();   // all warps done with smem from previous i

        // ---- first W prefetch for this i ----
        float4 wreg[4];
        w_prefetch(W, pbase + j0, tid, wreg);

        // ---- convert A = X[b0:b0+128, i, :] -> bf16 hi/lo smem (2 threads/row) ----
        {
            const int m  = tid >> 1;
            const int q0 = (tid & 1) * 8;
            const float4* xr = (const float4*)(X + (size_t)(b0 + m) * FD + i * DDIM) + q0;
            char* ahp = smem + SM_AH + m * ROWB + q0 * 8;
            char* alp = smem + SM_AL + m * ROWB + q0 * 8;
            #pragma unroll
            for (int q = 0; q < 8; q++) {
                float4 v = xr[q];
                uint2 h = make_uint2(packbf(v.x, v.y), packbf(v.z, v.w));
                uint2 l = make_uint2(packbf(v.x - bf_rt(v.x), v.y - bf_rt(v.y)),
                                     packbf(v.z - bf_rt(v.z), v.w - bf_rt(v.w)));
                *(uint2*)(ahp + q * 8) = h;
                *(uint2*)(alp + q * 8) = l;
            }
        }
        __syncthreads();

        // ---- A fragments in registers for whole j loop (warp owns 16 rows) ----
        uint32_t ah[4][4], al[4][4];
        {
            const int r16 = lane & 15;
            const int h16 = lane >> 4;
            const int m = wid * 16 + r16;
            #pragma unroll
            for (int kt = 0; kt < 4; kt++) {
                const uint32_t off = (uint32_t)(m * ROWB + kt * 32 + h16 * 16);
                LDSM_X4(ah[kt], sb + SM_AH + off);
                LDSM_X4(al[kt], sb + SM_AL + off);
            }
        }

        int buf = 0;
        for (int j = j0; j < FFEAT; j++, buf ^= 1) {
            const int p = pbase + j;

            // convert this j's W (registers -> smem buf), prefetch next j
            w_convert(smem, buf, tid, wreg);
            if (j + 1 < FFEAT) w_prefetch(W, p + 1, tid, wreg);
            __syncthreads();

            // ---- MMA: D = Xh Wh + Xl Wh + Xh Wl ----
            float acc[8][4];
            #pragma unroll
            for (int nt = 0; nt < 8; nt++)
                #pragma unroll
                for (int c = 0; c < 4; c++) acc[nt][c] = 0.f;

            const int kr = lane & 15;
            const int nh = lane >> 4;
            #pragma unroll
            for (int kt = 0; kt < 4; kt++) {
                #pragma unroll
                for (int nb = 0; nb < 4; nb++) {
                    uint32_t bh[4], bl[4];
                    const uint32_t off = (uint32_t)((kt * 16 + kr) * ROWB
                                                    + nb * 32 + nh * 16);
                    LDSM_X4_T(bh, sb + WBUF_HI(buf) + off);
                    LDSM_X4_T(bl, sb + WBUF_LO(buf) + off);
                    MMA16816(acc[2 * nb + 0], ah[kt], bh + 0);
                    MMA16816(acc[2 * nb + 1], ah[kt], bh + 2);
                    MMA16816(acc[2 * nb + 0], al[kt], bh + 0);
                    MMA16816(acc[2 * nb + 1], al[kt], bh + 2);
                    MMA16816(acc[2 * nb + 0], ah[kt], bl + 0);
                    MMA16816(acc[2 * nb + 1], ah[kt], bl + 2);
                }
            }

            // ---- epilogue: out[m, p, e] = D[m, e] * X[m, j, e] ----
            {
                const int tr = lane >> 2;
                const int tc = (lane & 3) * 2;
                const int m0 = b0 + wid * 16 + tr;
                const float* xj0 = X + (size_t)m0 * FD + j * DDIM;
                const float* xj1 = xj0 + 8 * FD;
                float* o0 = out + ((size_t)m0 * P_PAIRS + p) * DDIM;
                float* o1 = o0 + (size_t)8 * P_PAIRS * DDIM;
                #pragma unroll
                for (int nt = 0; nt < 8; nt++) {
                    const int e = nt * 8 + tc;
                    float2 x0 = *(const float2*)(xj0 + e);
                    float2 x1 = *(const float2*)(xj1 + e);
                    *(float2*)(o0 + e) = make_float2(acc[nt][0] * x0.x, acc[nt][1] * x0.y);
                    *(float2*)(o1 + e) = make_float2(acc[nt][2] * x1.x, acc[nt][3] * x1.y);
                }
            }
        }
    }
}

extern "C" void kernel_launch(void* const* d_in, const int* in_sizes, int n_in,
                              void* d_out, int out_size) {
    const float* X = (const float*)d_in[0];
    const float* W = (const float*)d_in[1];
    float* out = (float*)d_out;

    const int B = in_sizes[0] / FD;   // 4096

    cudaFuncSetAttribute(bilin_hmma2, cudaFuncAttributeMaxDynamicSharedMemorySize, SMEM_BYTES);

    dim3 grid(B / MT, 16);
    bilin_hmma2<<<grid, THREADS, SMEM_BYTES>>>(X, W, out);
}

// round 5
// speedup vs baseline: 1.0896x; 1.0896x over previous
#include <cuda_runtime.h>
#include <cuda_bf16.h>
#include <stdint.h>

#define FFEAT   32
#define DDIM    64
#define P_PAIRS 496
#define FD      (FFEAT * DDIM)   // 2048
#define MT      128
#define THREADS 128

#define APITCH 72                  // bf16 per row = 144 B
#define ROWB   (APITCH * 2)
#define SM_AH  0
#define SM_AL  (SM_AH + MT * ROWB)             // 18432
#define SM_W   (SM_AL + MT * ROWB)             // 36864
#define WBUF_HI(b) (SM_W + (b) * 18432)
#define WBUF_LO(b) (WBUF_HI(b) + 9216)
#define SM_RAW (SM_W + 2 * 18432)              // 73728
#define RAWBUF(b) (SM_RAW + (b) * 16384)
#define SMEM_BYTES (SM_RAW + 2 * 16384)        // 106496

static __device__ __forceinline__ uint32_t smem_u32(const void* p) {
    uint32_t a;
    asm("{ .reg .u64 t; cvta.to.shared.u64 t, %1; cvt.u32.u64 %0, t; }" : "=r"(a) : "l"(p));
    return a;
}
static __device__ __forceinline__ uint32_t packbf(float lo_e, float hi_e) {
    uint32_t r;
    asm("cvt.rn.bf16x2.f32 %0, %1, %2;" : "=r"(r) : "f"(hi_e), "f"(lo_e));
    return r;
}
static __device__ __forceinline__ float bf_rt(float x) {
    return __bfloat162float(__float2bfloat16(x));
}

#define LDSM_X4(r, addr)                                                     \
    asm volatile("ldmatrix.sync.aligned.m8n8.x4.shared.b16 {%0,%1,%2,%3}, [%4];" \
        : "=r"((r)[0]), "=r"((r)[1]), "=r"((r)[2]), "=r"((r)[3]) : "r"(addr))
#define LDSM_X4_T(r, addr)                                                   \
    asm volatile("ldmatrix.sync.aligned.m8n8.x4.trans.shared.b16 {%0,%1,%2,%3}, [%4];" \
        : "=r"((r)[0]), "=r"((r)[1]), "=r"((r)[2]), "=r"((r)[3]) : "r"(addr))
#define MMA16816(d, a, b)                                                    \
    asm volatile("mma.sync.aligned.m16n8k16.row.col.f32.bf16.bf16.f32 "      \
        "{%0,%1,%2,%3},{%4,%5,%6,%7},{%8,%9},{%0,%1,%2,%3};"                 \
        : "+f"((d)[0]), "+f"((d)[1]), "+f"((d)[2]), "+f"((d)[3])             \
        : "r"((a)[0]), "r"((a)[1]), "r"((a)[2]), "r"((a)[3]),                \
          "r"((b)[0]), "r"((b)[1]))

#define CP_ASYNC16(sm, gm) \
    asm volatile("cp.async.cg.shared.global [%0], [%1], 16;" :: "r"(sm), "l"(gm) : "memory")
#define CP_COMMIT()  asm volatile("cp.async.commit_group;" ::: "memory")
#define CP_WAIT1()   asm volatile("cp.async.wait_group 1;" ::: "memory")
#define CP_WAIT0()   asm volatile("cp.async.wait_group 0;" ::: "memory")

// issue this thread's 8 cp.asyncs for W_p into raw buffer b
static __device__ __forceinline__ void w_cpasync(uint32_t sb, int b, int tid,
                                                 const float* __restrict__ W, int p) {
    const char* wg = (const char*)(W + (size_t)p * DDIM * DDIM);
    #pragma unroll
    for (int t = 0; t < 8; t++) {
        const int idx4 = tid + (t << 7);
        CP_ASYNC16(sb + RAWBUF(b) + idx4 * 16, wg + idx4 * 16);
    }
    CP_COMMIT();
}
// convert this thread's own raw bytes (buffer b) into bf16 hi/lo tiles (buffer b)
static __device__ __forceinline__ void w_convert(char* smem, int b, int tid) {
    #pragma unroll
    for (int t = 0; t < 8; t++) {
        const int idx4 = tid + (t << 7);
        float4 v = *(const float4*)(smem + RAWBUF(b) + idx4 * 16);
        const int k  = idx4 >> 4;
        const int e4 = (idx4 & 15) << 2;
        uint2 h = make_uint2(packbf(v.x, v.y), packbf(v.z, v.w));
        uint2 l = make_uint2(packbf(v.x - bf_rt(v.x), v.y - bf_rt(v.y)),
                             packbf(v.z - bf_rt(v.z), v.w - bf_rt(v.w)));
        const uint32_t off = (uint32_t)(k * ROWB + e4 * 2);
        *(uint2*)(smem + WBUF_HI(b) + off) = h;
        *(uint2*)(smem + WBUF_LO(b) + off) = l;
    }
}

__global__ void __launch_bounds__(THREADS, 2)
bilin_hmma3(const float* __restrict__ X,   // [B, 32, 64]
            const float* __restrict__ W,   // [496, 64, 64]
            float* __restrict__ out)       // [B, 496, 64]
{
    extern __shared__ char smem[];
    const uint32_t sb  = smem_u32(smem);
    const int tid  = threadIdx.x;
    const int wid  = tid >> 5;
    const int lane = tid & 31;
    const int y    = blockIdx.y;           // 0..15
    const int b0   = blockIdx.x * MT;

    const int nI = (y == 15) ? 1 : 2;

    for (int s = 0; s < nI; s++) {
        const int i = (s == 0) ? y : 30 - y;
        const int pbase = i * (63 - i) / 2 - i - 1;   // p = pbase + j
        const int j0 = i + 1;

        if (s > 0) __syncthreads();

        // prime the W pipeline
        w_cpasync(sb, 0, tid, W, pbase + j0);

        // ---- convert A = X[b0:b0+128, i, :] -> bf16 hi/lo smem ----
        {
            const int m = tid;
            const float4* xr = (const float4*)(X + (size_t)(b0 + m) * FD + i * DDIM);
            char* ahp = smem + SM_AH + m * ROWB;
            char* alp = smem + SM_AL + m * ROWB;
            #pragma unroll
            for (int q = 0; q < 16; q++) {
                float4 v = xr[q];
                *(uint2*)(ahp + q * 8) = make_uint2(packbf(v.x, v.y), packbf(v.z, v.w));
                *(uint2*)(alp + q * 8) =
                    make_uint2(packbf(v.x - bf_rt(v.x), v.y - bf_rt(v.y)),
                               packbf(v.z - bf_rt(v.z), v.w - bf_rt(v.w)));
            }
        }
        __syncthreads();

        // ---- A fragments in registers for whole j loop (warp owns 32 rows) ----
        uint32_t ah[2][4][4], al[2][4][4];
        {
            const int r16 = lane & 15;
            const int h16 = lane >> 4;
            #pragma unroll
            for (int mt = 0; mt < 2; mt++) {
                const int m = wid * 32 + mt * 16 + r16;
                #pragma unroll
                for (int kt = 0; kt < 4; kt++) {
                    const uint32_t off = (uint32_t)(m * ROWB + kt * 32 + h16 * 16);
                    LDSM_X4(ah[mt][kt], sb + SM_AH + off);
                    LDSM_X4(al[mt][kt], sb + SM_AL + off);
                }
            }
        }

        int buf = 0;
        for (int j = j0; j < FFEAT; j++, buf ^= 1) {
            const int p = pbase + j;

            // prefetch next W, then wait for this one (own-bytes: no barrier needed)
            if (j + 1 < FFEAT) {
                w_cpasync(sb, buf ^ 1, tid, W, p + 1);
                CP_WAIT1();
            } else {
                CP_WAIT0();
            }
            w_convert(smem, buf, tid);
            __syncthreads();

            // ---- MMA: D = Xh Wh + Xl Wh + Xh Wl ----
            float acc[2][8][4];
            #pragma unroll
            for (int mt = 0; mt < 2; mt++)
                #pragma unroll
                for (int nt = 0; nt < 8; nt++)
                    #pragma unroll
                    for (int c = 0; c < 4; c++) acc[mt][nt][c] = 0.f;

            const int kr = lane & 15;
            const int nh = lane >> 4;
            #pragma unroll
            for (int kt = 0; kt < 4; kt++) {
                #pragma unroll
                for (int nb = 0; nb < 4; nb++) {
                    uint32_t bh[4], bl[4];
                    const uint32_t off = (uint32_t)((kt * 16 + kr) * ROWB
                                                    + nb * 32 + nh * 16);
                    LDSM_X4_T(bh, sb + WBUF_HI(buf) + off);
                    LDSM_X4_T(bl, sb + WBUF_LO(buf) + off);
                    #pragma unroll
                    for (int mt = 0; mt < 2; mt++) {
                        MMA16816(acc[mt][2 * nb + 0], ah[mt][kt], bh + 0);
                        MMA16816(acc[mt][2 * nb + 1], ah[mt][kt], bh + 2);
                        MMA16816(acc[mt][2 * nb + 0], al[mt][kt], bh + 0);
                        MMA16816(acc[mt][2 * nb + 1], al[mt][kt], bh + 2);
                        MMA16816(acc[mt][2 * nb + 0], ah[mt][kt], bl + 0);
                        MMA16816(acc[mt][2 * nb + 1], ah[mt][kt], bl + 2);
                    }
                }
            }

            // ---- epilogue: out[m, p, e] = D[m, e] * X[m, j, e] ----
            {
                const int tr = lane >> 2;
                const int tc = (lane & 3) * 2;
                #pragma unroll
                for (int mt = 0; mt < 2; mt++) {
                    const int m0 = b0 + wid * 32 + mt * 16 + tr;
                    const float* xj0 = X + (size_t)m0 * FD + j * DDIM;
                    const float* xj1 = xj0 + 8 * FD;
                    float* o0 = out + ((size_t)m0 * P_PAIRS + p) * DDIM;
                    float* o1 = o0 + (size_t)8 * P_PAIRS * DDIM;
                    #pragma unroll
                    for (int nt = 0; nt < 8; nt++) {
                        const int e = nt * 8 + tc;
                        float2 x0 = *(const float2*)(xj0 + e);
                        float2 x1 = *(const float2*)(xj1 + e);
                        *(float2*)(o0 + e) =
                            make_float2(acc[mt][nt][0] * x0.x, acc[mt][nt][1] * x0.y);
                        *(float2*)(o1 + e) =
                            make_float2(acc[mt][nt][2] * x1.x, acc[mt][nt][3] * x1.y);
                    }
                }
            }
        }
    }
}

extern "C" void kernel_launch(void* const* d_in, const int* in_sizes, int n_in,
                              void* d_out, int out_size) {
    const float* X = (const float*)d_in[0];
    const float* W = (const float*)d_in[1];
    float* out = (float*)d_out;

    const int B = in_sizes[0] / FD;   // 4096

    cudaFuncSetAttribute(bilin_hmma3, cudaFuncAttributeMaxDynamicSharedMemorySize, SMEM_BYTES);

    dim3 grid(B / MT, 16);
    bilin_hmma3<<<grid, THREADS, SMEM_BYTES>>>(X, W, out);
}

// round 6
// speedup vs baseline: 1.3031x; 1.1959x over previous
#include <cuda_runtime.h>
#include <cuda_bf16.h>
#include <stdint.h>

#define FFEAT   32
#define DDIM    64
#define P_PAIRS 496
#define FD      (FFEAT * DDIM)   // 2048
#define MT      128
#define THREADS 128

// smem: A_hi[128][72]bf16, A_lo, W_hi[64][72]bf16, W_lo  (pitch 72 = conflict-free ldmatrix)
#define APITCH 72
#define ROWB   (APITCH * 2)
#define SM_AH  0
#define SM_AL  (SM_AH + MT * ROWB)            // 18432
#define SM_WH  (SM_AL + MT * ROWB)            // 36864
#define SM_WL  (SM_WH + DDIM * ROWB)          // 46080
#define SMEM_BYTES (SM_WL + DDIM * ROWB)      // 55296

static __device__ __forceinline__ uint32_t smem_u32(const void* p) {
    uint32_t a;
    asm("{ .reg .u64 t; cvta.to.shared.u64 t, %1; cvt.u32.u64 %0, t; }" : "=r"(a) : "l"(p));
    return a;
}
static __device__ __forceinline__ uint32_t packbf(float lo_e, float hi_e) {
    uint32_t r;
    asm("cvt.rn.bf16x2.f32 %0, %1, %2;" : "=r"(r) : "f"(hi_e), "f"(lo_e));
    return r;
}
static __device__ __forceinline__ float bf_rt(float x) {
    return __bfloat162float(__float2bfloat16(x));
}

#define LDSM_X4(r, addr)                                                     \
    asm volatile("ldmatrix.sync.aligned.m8n8.x4.shared.b16 {%0,%1,%2,%3}, [%4];" \
        : "=r"((r)[0]), "=r"((r)[1]), "=r"((r)[2]), "=r"((r)[3]) : "r"(addr))
#define LDSM_X4_T(r, addr)                                                   \
    asm volatile("ldmatrix.sync.aligned.m8n8.x4.trans.shared.b16 {%0,%1,%2,%3}, [%4];" \
        : "=r"((r)[0]), "=r"((r)[1]), "=r"((r)[2]), "=r"((r)[3]) : "r"(addr))
#define MMA16816(d, a, b)                                                    \
    asm volatile("mma.sync.aligned.m16n8k16.row.col.f32.bf16.bf16.f32 "      \
        "{%0,%1,%2,%3},{%4,%5,%6,%7},{%8,%9},{%0,%1,%2,%3};"                 \
        : "+f"((d)[0]), "+f"((d)[1]), "+f"((d)[2]), "+f"((d)[3])             \
        : "r"((a)[0]), "r"((a)[1]), "r"((a)[2]), "r"((a)[3]),                \
          "r"((b)[0]), "r"((b)[1]))

__global__ void __launch_bounds__(THREADS, 2)
bilin_hmma4(const float* __restrict__ X,   // [B, 32, 64]
            const float* __restrict__ W,   // [496, 64, 64]
            float* __restrict__ out)       // [B, 496, 64]
{
    extern __shared__ char smem[];
    const uint32_t sb  = smem_u32(smem);
    const int tid  = threadIdx.x;
    const int wid  = tid >> 5;
    const int lane = tid & 31;
    const int i    = blockIdx.y;
    const int b0   = blockIdx.x * MT;

    // ---- convert A = X[b0:b0+128, i, :] to bf16 hi/lo smem (once) ----
    {
        const int m = tid;
        const float4* xr = (const float4*)(X + (size_t)(b0 + m) * FD + i * DDIM);
        char* ahp = smem + SM_AH + m * ROWB;
        char* alp = smem + SM_AL + m * ROWB;
        #pragma unroll
        for (int q = 0; q < 16; q++) {
            float4 v = xr[q];
            *(uint2*)(ahp + q * 8) = make_uint2(packbf(v.x, v.y), packbf(v.z, v.w));
            *(uint2*)(alp + q * 8) =
                make_uint2(packbf(v.x - bf_rt(v.x), v.y - bf_rt(v.y)),
                           packbf(v.z - bf_rt(v.z), v.w - bf_rt(v.w)));
        }
    }
    __syncthreads();

    // ---- A fragments in registers for the whole j loop (warp owns 32 rows) ----
    uint32_t ah[2][4][4], al[2][4][4];
    {
        const int r16 = lane & 15;
        const int h16 = lane >> 4;
        #pragma unroll
        for (int mt = 0; mt < 2; mt++) {
            const int m = wid * 32 + mt * 16 + r16;
            #pragma unroll
            for (int kt = 0; kt < 4; kt++) {
                const uint32_t off = (uint32_t)(m * ROWB + kt * 32 + h16 * 16);
                LDSM_X4(ah[mt][kt], sb + SM_AH + off);
                LDSM_X4(al[mt][kt], sb + SM_AL + off);
            }
        }
    }

    const int pbase = i * (63 - i) / 2 - i - 1;   // p = pbase + j

    for (int j = i + 1; j < FFEAT; j++) {
        const int p = pbase + j;

        __syncthreads();   // prior iteration's ldmatrix reads of W done
        // ---- convert W_p -> bf16 hi/lo smem [k][n] (coalesced LDG.128) ----
        {
            const float4* wg = (const float4*)(W + (size_t)p * DDIM * DDIM);
            #pragma unroll
            for (int t = 0; t < 8; t++) {
                const int idx4 = tid + (t << 7);      // 0..1023
                const int k  = idx4 >> 4;
                const int e4 = (idx4 & 15) << 2;
                float4 v = wg[idx4];
                const uint32_t off = (uint32_t)(k * ROWB + e4 * 2);
                *(uint2*)(smem + SM_WH + off) =
                    make_uint2(packbf(v.x, v.y), packbf(v.z, v.w));
                *(uint2*)(smem + SM_WL + off) =
                    make_uint2(packbf(v.x - bf_rt(v.x), v.y - bf_rt(v.y)),
                               packbf(v.z - bf_rt(v.z), v.w - bf_rt(v.w)));
            }
        }
        __syncthreads();

        // ---- accumulate D = Xh Wh + Xl Wh + Xh Wl (latency-aware schedule) ----
        float acc[2][8][4];
        #pragma unroll
        for (int mt = 0; mt < 2; mt++)
            #pragma unroll
            for (int nt = 0; nt < 8; nt++)
                #pragma unroll
                for (int c = 0; c < 4; c++) acc[mt][nt][c] = 0.f;

        const int kr = lane & 15;
        const int nh = lane >> 4;
        #pragma unroll
        for (int kt = 0; kt < 4; kt++) {
            // front-load all B fragments for this kt (8 transposed LDSMs)
            uint32_t bh[4][4], bl[4][4];
            #pragma unroll
            for (int nb = 0; nb < 4; nb++) {
                const uint32_t off = (uint32_t)((kt * 16 + kr) * ROWB
                                                + nb * 32 + nh * 16);
                LDSM_X4_T(bh[nb], sb + SM_WH + off);
                LDSM_X4_T(bl[nb], sb + SM_WL + off);
            }
            // sweep 1: Xh*Wh over all 16 independent acc tiles
            #pragma unroll
            for (int mt = 0; mt < 2; mt++)
                #pragma unroll
                for (int nb = 0; nb < 4; nb++) {
                    MMA16816(acc[mt][2 * nb + 0], ah[mt][kt], bh[nb] + 0);
                    MMA16816(acc[mt][2 * nb + 1], ah[mt][kt], bh[nb] + 2);
                }
            // sweep 2: Xl*Wh
            #pragma unroll
            for (int mt = 0; mt < 2; mt++)
                #pragma unroll
                for (int nb = 0; nb < 4; nb++) {
                    MMA16816(acc[mt][2 * nb + 0], al[mt][kt], bh[nb] + 0);
                    MMA16816(acc[mt][2 * nb + 1], al[mt][kt], bh[nb] + 2);
                }
            // sweep 3: Xh*Wl
            #pragma unroll
            for (int mt = 0; mt < 2; mt++)
                #pragma unroll
                for (int nb = 0; nb < 4; nb++) {
                    MMA16816(acc[mt][2 * nb + 0], ah[mt][kt], bl[nb] + 0);
                    MMA16816(acc[mt][2 * nb + 1], ah[mt][kt], bl[nb] + 2);
                }
        }

        // ---- epilogue: out[m, p, e] = D[m, e] * X[m, j, e] ----
        {
            const int tr = lane >> 2;
            const int tc = (lane & 3) * 2;
            #pragma unroll
            for (int mt = 0; mt < 2; mt++) {
                const int m0 = b0 + wid * 32 + mt * 16 + tr;
                const float* xj0 = X + (size_t)m0 * FD + j * DDIM;
                const float* xj1 = xj0 + 8 * FD;
                float* o0 = out + ((size_t)m0 * P_PAIRS + p) * DDIM;
                float* o1 = o0 + (size_t)8 * P_PAIRS * DDIM;
                #pragma unroll
                for (int nt = 0; nt < 8; nt++) {
                    const int e = nt * 8 + tc;
                    float2 x0 = *(const float2*)(xj0 + e);
                    float2 x1 = *(const float2*)(xj1 + e);
                    *(float2*)(o0 + e) =
                        make_float2(acc[mt][nt][0] * x0.x, acc[mt][nt][1] * x0.y);
                    *(float2*)(o1 + e) =
                        make_float2(acc[mt][nt][2] * x1.x, acc[mt][nt][3] * x1.y);
                }
            }
        }
    }
}

extern "C" void kernel_launch(void* const* d_in, const int* in_sizes, int n_in,
                              void* d_out, int out_size) {
    const float* X = (const float*)d_in[0];
    const float* W = (const float*)d_in[1];
    float* out = (float*)d_out;

    const int B = in_sizes[0] / FD;   // 4096

    cudaFuncSetAttribute(bilin_hmma4, cudaFuncAttributeMaxDynamicSharedMemorySize, SMEM_BYTES);

    dim3 grid(B / MT, FFEAT - 1);
    bilin_hmma4<<<grid, THREADS, SMEM_BYTES>>>(X, W, out);
}

// round 7
// speedup vs baseline: 1.4027x; 1.0765x over previous
#include <cuda_runtime.h>
#include <cuda_bf16.h>
#include <stdint.h>

#define FFEAT   32
#define DDIM    64
#define P_PAIRS 496
#define FD      (FFEAT * DDIM)   // 2048
#define MT      128
#define THREADS 128

// smem: A_hi[128][72]bf16, A_lo, W_hi[64][72]bf16, W_lo, staging[4][16][68]f32
#define APITCH 72
#define ROWB   (APITCH * 2)
#define SM_AH  0
#define SM_AL  (SM_AH + MT * ROWB)            // 18432
#define SM_WH  (SM_AL + MT * ROWB)            // 36864
#define SM_WL  (SM_WH + DDIM * ROWB)          // 46080
#define SM_ST  (SM_WL + DDIM * ROWB)          // 55296
#define STPITCH 68                             // floats, bank-spread
#define ST_WARP (16 * STPITCH * 4)             // 4352 B per warp
#define SMEM_BYTES (SM_ST + 4 * ST_WARP)       // 72704

static __device__ __forceinline__ uint32_t smem_u32(const void* p) {
    uint32_t a;
    asm("{ .reg .u64 t; cvta.to.shared.u64 t, %1; cvt.u32.u64 %0, t; }" : "=r"(a) : "l"(p));
    return a;
}
static __device__ __forceinline__ uint32_t packbf(float lo_e, float hi_e) {
    uint32_t r;
    asm("cvt.rn.bf16x2.f32 %0, %1, %2;" : "=r"(r) : "f"(hi_e), "f"(lo_e));
    return r;
}
static __device__ __forceinline__ float bf_rt(float x) {
    return __bfloat162float(__float2bfloat16(x));
}

#define LDSM_X4(r, addr)                                                     \
    asm volatile("ldmatrix.sync.aligned.m8n8.x4.shared.b16 {%0,%1,%2,%3}, [%4];" \
        : "=r"((r)[0]), "=r"((r)[1]), "=r"((r)[2]), "=r"((r)[3]) : "r"(addr))
#define LDSM_X4_T(r, addr)                                                   \
    asm volatile("ldmatrix.sync.aligned.m8n8.x4.trans.shared.b16 {%0,%1,%2,%3}, [%4];" \
        : "=r"((r)[0]), "=r"((r)[1]), "=r"((r)[2]), "=r"((r)[3]) : "r"(addr))
#define MMA16816(d, a, b)                                                    \
    asm volatile("mma.sync.aligned.m16n8k16.row.col.f32.bf16.bf16.f32 "      \
        "{%0,%1,%2,%3},{%4,%5,%6,%7},{%8,%9},{%0,%1,%2,%3};"                 \
        : "+f"((d)[0]), "+f"((d)[1]), "+f"((d)[2]), "+f"((d)[3])             \
        : "r"((a)[0]), "r"((a)[1]), "r"((a)[2]), "r"((a)[3]),                \
          "r"((b)[0]), "r"((b)[1]))

__global__ void __launch_bounds__(THREADS, 2)
bilin_hmma5(const float* __restrict__ X,   // [B, 32, 64]
            const float* __restrict__ W,   // [496, 64, 64]
            float* __restrict__ out)       // [B, 496, 64]
{
    extern __shared__ char smem[];
    const uint32_t sb  = smem_u32(smem);
    const int tid  = threadIdx.x;
    const int wid  = tid >> 5;
    const int lane = tid & 31;
    const int i    = blockIdx.y;
    const int b0   = blockIdx.x * MT;

    // ---- convert A = X[b0:b0+128, i, :] to bf16 hi/lo smem (once) ----
    {
        const int m = tid;
        const float4* xr = (const float4*)(X + (size_t)(b0 + m) * FD + i * DDIM);
        char* ahp = smem + SM_AH + m * ROWB;
        char* alp = smem + SM_AL + m * ROWB;
        #pragma unroll
        for (int q = 0; q < 16; q++) {
            float4 v = xr[q];
            *(uint2*)(ahp + q * 8) = make_uint2(packbf(v.x, v.y), packbf(v.z, v.w));
            *(uint2*)(alp + q * 8) =
                make_uint2(packbf(v.x - bf_rt(v.x), v.y - bf_rt(v.y)),
                           packbf(v.z - bf_rt(v.z), v.w - bf_rt(v.w)));
        }
    }
    __syncthreads();

    // ---- A fragments in registers for the whole j loop (warp owns 32 rows) ----
    uint32_t ah[2][4][4], al[2][4][4];
    {
        const int r16 = lane & 15;
        const int h16 = lane >> 4;
        #pragma unroll
        for (int mt = 0; mt < 2; mt++) {
            const int m = wid * 32 + mt * 16 + r16;
            #pragma unroll
            for (int kt = 0; kt < 4; kt++) {
                const uint32_t off = (uint32_t)(m * ROWB + kt * 32 + h16 * 16);
                LDSM_X4(ah[mt][kt], sb + SM_AH + off);
                LDSM_X4(al[mt][kt], sb + SM_AL + off);
            }
        }
    }

    const int pbase = i * (63 - i) / 2 - i - 1;   // p = pbase + j

    for (int j = i + 1; j < FFEAT; j++) {
        const int p = pbase + j;

        __syncthreads();   // prior iteration's ldmatrix reads of W done
        // ---- convert W_p -> bf16 hi/lo smem [k][n] (coalesced LDG.128) ----
        {
            const float4* wg = (const float4*)(W + (size_t)p * DDIM * DDIM);
            #pragma unroll
            for (int t = 0; t < 8; t++) {
                const int idx4 = tid + (t << 7);      // 0..1023
                const int k  = idx4 >> 4;
                const int e4 = (idx4 & 15) << 2;
                float4 v = wg[idx4];
                const uint32_t off = (uint32_t)(k * ROWB + e4 * 2);
                *(uint2*)(smem + SM_WH + off) =
                    make_uint2(packbf(v.x, v.y), packbf(v.z, v.w));
                *(uint2*)(smem + SM_WL + off) =
                    make_uint2(packbf(v.x - bf_rt(v.x), v.y - bf_rt(v.y)),
                               packbf(v.z - bf_rt(v.z), v.w - bf_rt(v.w)));
            }
        }
        __syncthreads();

        // ---- accumulate D = Xh Wh + Xl Wh + Xh Wl ----
        float acc[2][8][4];
        #pragma unroll
        for (int mt = 0; mt < 2; mt++)
            #pragma unroll
            for (int nt = 0; nt < 8; nt++)
                #pragma unroll
                for (int c = 0; c < 4; c++) acc[mt][nt][c] = 0.f;

        const int kr = lane & 15;
        const int nh = lane >> 4;
        #pragma unroll
        for (int kt = 0; kt < 4; kt++) {
            uint32_t bh[4][4], bl[4][4];
            #pragma unroll
            for (int nb = 0; nb < 4; nb++) {
                const uint32_t off = (uint32_t)((kt * 16 + kr) * ROWB
                                                + nb * 32 + nh * 16);
                LDSM_X4_T(bh[nb], sb + SM_WH + off);
                LDSM_X4_T(bl[nb], sb + SM_WL + off);
            }
            #pragma unroll
            for (int mt = 0; mt < 2; mt++)
                #pragma unroll
                for (int nb = 0; nb < 4; nb++) {
                    MMA16816(acc[mt][2 * nb + 0], ah[mt][kt], bh[nb] + 0);
                    MMA16816(acc[mt][2 * nb + 1], ah[mt][kt], bh[nb] + 2);
                }
            #pragma unroll
            for (int mt = 0; mt < 2; mt++)
                #pragma unroll
                for (int nb = 0; nb < 4; nb++) {
                    MMA16816(acc[mt][2 * nb + 0], al[mt][kt], bh[nb] + 0);
                    MMA16816(acc[mt][2 * nb + 1], al[mt][kt], bh[nb] + 2);
                }
            #pragma unroll
            for (int mt = 0; mt < 2; mt++)
                #pragma unroll
                for (int nb = 0; nb < 4; nb++) {
                    MMA16816(acc[mt][2 * nb + 0], ah[mt][kt], bl[nb] + 0);
                    MMA16816(acc[mt][2 * nb + 1], ah[mt][kt], bl[nb] + 2);
                }
        }

        // ---- epilogue: stage D half-tile in smem, then coalesced xj/out ----
        {
            char* stw = smem + SM_ST + wid * ST_WARP;
            const int tr = lane >> 2;
            const int tc = (lane & 3) * 2;
            const int r2 = lane >> 4;          // 0/1: row within a 2-row step
            const int c4 = (lane & 15) * 4;    // col within a row
            #pragma unroll
            for (int mt = 0; mt < 2; mt++) {
                __syncwarp();   // staging buffer free (prev mt's reads done)
                #pragma unroll
                for (int nt = 0; nt < 8; nt++) {
                    *(float2*)(stw + (tr * STPITCH + nt * 8 + tc) * 4) =
                        make_float2(acc[mt][nt][0], acc[mt][nt][1]);
                    *(float2*)(stw + ((tr + 8) * STPITCH + nt * 8 + tc) * 4) =
                        make_float2(acc[mt][nt][2], acc[mt][nt][3]);
                }
                __syncwarp();
                #pragma unroll
                for (int s2 = 0; s2 < 8; s2++) {
                    const int r  = s2 * 2 + r2;                 // 0..15
                    const int m0 = b0 + wid * 32 + mt * 16 + r;
                    float4 d  = *(const float4*)(stw + (r * STPITCH + c4) * 4);
                    float4 xv = *(const float4*)(X + (size_t)m0 * FD + j * DDIM + c4);
                    float4 o  = make_float4(d.x * xv.x, d.y * xv.y,
                                            d.z * xv.z, d.w * xv.w);
                    *(float4*)(out + ((size_t)m0 * P_PAIRS + p) * DDIM + c4) = o;
                }
            }
        }
    }
}

extern "C" void kernel_launch(void* const* d_in, const int* in_sizes, int n_in,
                              void* d_out, int out_size) {
    const float* X = (const float*)d_in[0];
    const float* W = (const float*)d_in[1];
    float* out = (float*)d_out;

    const int B = in_sizes[0] / FD;   // 4096

    cudaFuncSetAttribute(bilin_hmma5, cudaFuncAttributeMaxDynamicSharedMemorySize, SMEM_BYTES);

    dim3 grid(B / MT, FFEAT - 1);
    bilin_hmma5<<<grid, THREADS, SMEM_BYTES>>>(X, W, out);
}